// round 16
// baseline (speedup 1.0000x reference)
#include <cuda_runtime.h>
#include <cuda_bf16.h>
#include <cstdint>

#define BN    8192
#define DIM   128
#define TOPK  128
#define CAP   2048
#define ASTR  136
#define NT    64
#define NTRI  (NT * (NT + 1) / 2)   // 2080 triangular tiles
#define K0RAW 0x3E20                // bf16 raw bits of 0.15625
#define KK    ((K0RAW << 16) | K0RAW)

// -------- device scratch --------
__device__ __nv_bfloat16  g_fnb[(size_t)BN * DIM];
__device__ unsigned char  g_lab[BN];
__device__ float          g_cent[256 * DIM];
__device__ int            g_ccnt[BN];
__device__ unsigned short g_cand[(size_t)BN * CAP];   // 32 MB candidate keys
__device__ float          g_partial[BN];

// ============================ helpers ============================
__device__ __forceinline__ uint32_t smem_u32(const void* p) {
    uint32_t a;
    asm("{ .reg .u64 t; cvta.to.shared.u64 t, %1; cvt.u32.u64 %0, t; }" : "=r"(a) : "l"(p));
    return a;
}
__device__ __forceinline__ unsigned pack_bf16x2(float lo, float hi) {
    unsigned r;
    asm("cvt.rn.bf16x2.f32 %0, %1, %2;" : "=r"(r) : "f"(hi), "f"(lo));
    return r;
}
__device__ __forceinline__ void ldmatrix_x4(uint32_t& r0, uint32_t& r1, uint32_t& r2, uint32_t& r3, uint32_t a) {
    asm volatile("ldmatrix.sync.aligned.m8n8.x4.shared.b16 {%0,%1,%2,%3}, [%4];"
                 : "=r"(r0), "=r"(r1), "=r"(r2), "=r"(r3) : "r"(a));
}
__device__ __forceinline__ void ldmatrix_x2(uint32_t& r0, uint32_t& r1, uint32_t a) {
    asm volatile("ldmatrix.sync.aligned.m8n8.x2.shared.b16 {%0,%1}, [%2];"
                 : "=r"(r0), "=r"(r1) : "r"(a));
}
__device__ __forceinline__ void mma_bf16(float* d, const uint32_t* a, const uint32_t* b) {
    asm volatile(
        "mma.sync.aligned.m16n8k16.row.col.f32.bf16.bf16.f32 "
        "{%0,%1,%2,%3}, {%4,%5,%6,%7}, {%8,%9}, {%0,%1,%2,%3};"
        : "+f"(d[0]), "+f"(d[1]), "+f"(d[2]), "+f"(d[3])
        : "r"(a[0]), "r"(a[1]), "r"(a[2]), "r"(a[3]), "r"(b[0]), "r"(b[1]));
}

__device__ __forceinline__ unsigned fkey16(unsigned x) {
    return (x ^ (0x8000u | (0x7FFFu & (0u - (x >> 15))))) & 0xFFFFu;
}
__device__ __forceinline__ float val16(unsigned k) {
    unsigned b = (k & 0x8000u) ? (k ^ 0x8000u) : ((~k) & 0xFFFFu);
    return __uint_as_float(b << 16);
}
// exact fixed-point (val * 2^13) for keys above K0 (exponent >= 124)
__device__ __forceinline__ long long ival16(unsigned k) {
    unsigned raw = k & 0x7FFFu;
    int E = (int)(raw >> 7);
    int M = 128 + (int)(raw & 127u);
    return (long long)M << (E - 121);
}
__device__ __forceinline__ float bflo(unsigned x) { return __uint_as_float(x << 16); }
__device__ __forceinline__ float bfhi(unsigned x) { return __uint_as_float(x & 0xFFFF0000u); }

// ============================ prep: normalize + labels + counter zero ============================
__global__ void prep_kernel(const float* __restrict__ feats, const unsigned* __restrict__ words) {
    if (blockIdx.x == 1024) {
        int tid = threadIdx.x;
        int any = 0;
        for (int i = tid; i < BN / 2; i += blockDim.x) any |= (words[2 * i + 1] != 0u);
        int tot  = __syncthreads_or(any);
        int is64 = (tot == 0);
        for (int i = tid; i < BN; i += blockDim.x)
            g_lab[i] = (unsigned char)(is64 ? words[2 * i] : words[i]);
        for (int i = tid; i < BN; i += blockDim.x) g_ccnt[i] = 0;
        return;
    }
    int w    = (blockIdx.x * blockDim.x + threadIdx.x) >> 5;
    int lane = threadIdx.x & 31;
    float4 v = ((const float4*)(feats + (size_t)w * DIM))[lane];
    float ss = v.x * v.x + v.y * v.y + v.z * v.z + v.w * v.w;
    #pragma unroll
    for (int o = 16; o; o >>= 1) ss += __shfl_xor_sync(0xffffffffu, ss, o);
    float inv = rsqrtf(ss);
    unsigned* dst = (unsigned*)(g_fnb + (size_t)w * DIM);
    dst[lane * 2 + 0] = pack_bf16x2(v.x * inv, v.y * inv);
    dst[lane * 2 + 1] = pack_bf16x2(v.z * inv, v.w * inv);
}

// ============================ class centroids ============================
__global__ void __launch_bounds__(256) centroid_kernel() {
    __shared__ unsigned short idx[BN];
    __shared__ float cpart[2][DIM];
    __shared__ int wcnt8[8];

    int l = blockIdx.x, tid = threadIdx.x, lane = tid & 31, w = tid >> 5;
    unsigned char lc = (unsigned char)l;
    unsigned lw = (unsigned)lc * 0x01010101u;
    const unsigned* LW = (const unsigned*)g_lab;

    int cnt = 0;
    #pragma unroll 4
    for (int k = 0; k < 8; k++) {
        unsigned e = __vcmpeq4(__ldg(&LW[w * 256 + k * 32 + lane]), lw);
        cnt += __popc(e) >> 3;
    }
    #pragma unroll
    for (int o = 16; o; o >>= 1) cnt += __shfl_xor_sync(0xffffffffu, cnt, o);
    if (lane == 0) wcnt8[w] = cnt;
    __syncthreads();

    int base = 0;
    #pragma unroll
    for (int ww = 0; ww < 8; ww++) if (ww < w) base += wcnt8[ww];
    int total = 0;
    #pragma unroll
    for (int ww = 0; ww < 8; ww++) total += wcnt8[ww];

    int pos = base;
    for (int k = 0; k < 32; k++) {
        int j = w * 1024 + k * 32 + lane;
        bool m = (g_lab[j] == lc);
        unsigned bm = __ballot_sync(0xffffffffu, m);
        if (m) idx[pos + __popc(bm & ((1u << lane) - 1u))] = (unsigned short)j;
        pos += __popc(bm);
    }
    __syncthreads();

    int half = tid >> 7;
    int d = tid & 127;
    const unsigned short* F16 = (const unsigned short*)g_fnb;
    float c = 0.f;
    int t = half;
    for (; t + 6 < total; t += 8) {
        float a0 = __uint_as_float(((unsigned)__ldg(&F16[(size_t)idx[t]     * DIM + d])) << 16);
        float a1 = __uint_as_float(((unsigned)__ldg(&F16[(size_t)idx[t + 2] * DIM + d])) << 16);
        float a2 = __uint_as_float(((unsigned)__ldg(&F16[(size_t)idx[t + 4] * DIM + d])) << 16);
        float a3 = __uint_as_float(((unsigned)__ldg(&F16[(size_t)idx[t + 6] * DIM + d])) << 16);
        c += a0; c += a1; c += a2; c += a3;
    }
    for (; t < total; t += 2)
        c += __uint_as_float(((unsigned)__ldg(&F16[(size_t)idx[t] * DIM + d])) << 16);
    cpart[half][d] = c;
    __syncthreads();
    if (tid < DIM) g_cent[l * DIM + tid] = cpart[0][tid] + cpart[1][tid];
}

// ============================ GEMM + half-warp cooperative candidate filter ============================
__global__ void __launch_bounds__(256, 2) gemm_mma_kernel() {
    int rem = blockIdx.x, tm = 0;
    #pragma unroll 1
    while (rem >= NT - tm) { rem -= NT - tm; tm++; }
    int tn = tm + rem;

    extern __shared__ __align__(16) char sm[];
    __nv_bfloat16* Asm = (__nv_bfloat16*)sm;
    __nv_bfloat16* Bsm = (tm == tn) ? Asm : (__nv_bfloat16*)(sm + 128 * ASTR * 2);

    int tid  = threadIdx.x;
    int wid  = tid >> 5, lane = tid & 31;
    int wm   = wid >> 2, wn = wid & 3;

    const uint4* F = (const uint4*)g_fnb;
    #pragma unroll
    for (int it = 0; it < 8; it++) {
        int i = tid + it * 256;
        int r = i >> 4, g = i & 15;
        *(uint4*)(Asm + r * ASTR + g * 8) = F[(size_t)(tm * 128 + r) * 16 + g];
    }
    if (tm != tn) {
        #pragma unroll
        for (int it = 0; it < 8; it++) {
            int i = tid + it * 256;
            int r = i >> 4, g = i & 15;
            *(uint4*)(Bsm + r * ASTR + g * 8) = F[(size_t)(tn * 128 + r) * 16 + g];
        }
    }
    __syncthreads();

    float acc[4][4][4];
    #pragma unroll
    for (int i = 0; i < 4; i++)
        #pragma unroll
        for (int j = 0; j < 4; j++)
            #pragma unroll
            for (int c = 0; c < 4; c++) acc[i][j][c] = 0.f;

    uint32_t a_base = smem_u32(Asm) + ((wm * 64 + (lane & 15)) * ASTR + (lane >> 4) * 8) * 2;
    uint32_t b_base = smem_u32(Bsm) + ((wn * 32 + (lane & 7)) * ASTR + ((lane >> 3) & 1) * 8) * 2;

    #pragma unroll
    for (int k0 = 0; k0 < DIM; k0 += 16) {
        uint32_t af[4][4], bf[4][2];
        #pragma unroll
        for (int mt = 0; mt < 4; mt++)
            ldmatrix_x4(af[mt][0], af[mt][1], af[mt][2], af[mt][3],
                        a_base + (mt * 16 * ASTR + k0) * 2);
        #pragma unroll
        for (int nt = 0; nt < 4; nt++)
            ldmatrix_x2(bf[nt][0], bf[nt][1],
                        b_base + (nt * 8 * ASTR + k0) * 2);
        #pragma unroll
        for (int mt = 0; mt < 4; mt++)
            #pragma unroll
            for (int nt = 0; nt < 4; nt++)
                mma_bf16(acc[mt][nt], af[mt], bf[nt]);
    }
    __syncthreads();   // A/B smem dead; reuse for staging

    // ---- stage results: bf16 [128][136] + (off-diag) XOR-swizzled transpose ----
    __nv_bfloat16*  stage = (__nv_bfloat16*)sm;                 // 34816 B
    unsigned short* st2   = (unsigned short*)(sm + 34816);      // 32768 B
    bool mir = (tm != tn);

    #pragma unroll
    for (int mt = 0; mt < 4; mt++) {
        int r0 = wm * 64 + mt * 16 + (lane >> 2);
        #pragma unroll
        for (int nt = 0; nt < 4; nt++) {
            int c0 = wn * 32 + nt * 8 + (lane & 3) * 2;
            unsigned p0 = pack_bf16x2(acc[mt][nt][0], acc[mt][nt][1]);
            unsigned p1 = pack_bf16x2(acc[mt][nt][2], acc[mt][nt][3]);
            *(unsigned*)&stage[r0 * ASTR + c0]       = p0;
            *(unsigned*)&stage[(r0 + 8) * ASTR + c0] = p1;
            if (mir) {
                int ra = r0, rb = r0 + 8;
                st2[(c0)     * 128 + (((ra >> 3) ^ (c0 & 15)) * 8)       + (ra & 7)] = (unsigned short)(p0 & 0xFFFF);
                st2[(c0 + 1) * 128 + (((ra >> 3) ^ ((c0 + 1) & 15)) * 8) + (ra & 7)] = (unsigned short)(p0 >> 16);
                st2[(c0)     * 128 + (((rb >> 3) ^ (c0 & 15)) * 8)       + (rb & 7)] = (unsigned short)(p1 & 0xFFFF);
                st2[(c0 + 1) * 128 + (((rb >> 3) ^ ((c0 + 1) & 15)) * 8) + (rb & 7)] = (unsigned short)(p1 >> 16);
            }
        }
    }
    __syncthreads();
    if (!mir && tid < 128) stage[tid * ASTR + tid] = __ushort_as_bfloat16(0);  // diag -> fails filter
    __syncthreads();

    // ---- half-warp cooperative scan & publish: conflict-light, 1 atomic/row/CTA ----
    {
        int hl   = lane & 15;          // half-lane
        int half = lane >> 4;
        int nrows = mir ? 256 : 128;
        for (int rr = wid * 2 + half; rr < nrows; rr += 16) {
            uint4 v;
            int grow;
            if (rr < 128) {
                v = ((const uint4*)&stage[rr * ASTR])[hl];
                grow = tm * 128 + rr;
            } else {
                int t = rr - 128;
                int pg = hl ^ (t & 15);
                v = *(const uint4*)&st2[t * 128 + pg * 8];
                grow = tn * 128 + t;
            }
            unsigned m0 = __vcmpgts2(v.x, KK), m1 = __vcmpgts2(v.y, KK);
            unsigned m2 = __vcmpgts2(v.z, KK), m3 = __vcmpgts2(v.w, KK);
            int cnt = __popc(m0 & 0x80008000u) + __popc(m1 & 0x80008000u)
                    + __popc(m2 & 0x80008000u) + __popc(m3 & 0x80008000u);
            // inclusive scan over 16-lane half
            int incl = cnt;
            #pragma unroll
            for (int off = 1; off < 16; off <<= 1) {
                int u = __shfl_up_sync(0xffffffffu, incl, off);
                if (hl >= off) incl += u;
            }
            int total = __shfl_sync(0xffffffffu, incl, (lane & 16) | 15);
            int q = 0;
            if (hl == 0 && total > 0) q = atomicAdd(&g_ccnt[grow], total);
            q = __shfl_sync(0xffffffffu, q, lane & 16);
            if (cnt > 0) {
                int pos = q + incl - cnt;
                unsigned short* dst = g_cand + (size_t)grow * CAP;
                unsigned ps[4] = {v.x, v.y, v.z, v.w};
                unsigned ms[4] = {m0, m1, m2, m3};
                #pragma unroll
                for (int k = 0; k < 4; k++) {
                    if (ms[k] & 0x8000u)     { if (pos < CAP) dst[pos] = (unsigned short)(ps[k] | 0x8000u); pos++; }
                    if (ms[k] & 0x80000000u) { if (pos < CAP) dst[pos] = (unsigned short)((ps[k] >> 16) | 0x8000u); pos++; }
                }
            }
        }
    }
}

// ============================ select: warp per row over candidate lists ============================
__global__ void __launch_bounds__(512) select_kernel() {
    __shared__ unsigned hist[16][512];   // 32 KB

    int tid = threadIdx.x, lane = tid & 31, w = tid >> 5;
    int r = blockIdx.x * 16 + w;

    int cnt = g_ccnt[r];
    const unsigned short* cl = g_cand + (size_t)r * CAP;
    bool ok = (cnt >= TOPK && cnt <= CAP);
    double rowsum = 0.0;                  // valid on lane 0

    if (ok) {
        #pragma unroll
        for (int i = lane; i < 512; i += 32) hist[w][i] = 0;
        __syncwarp();
        for (int t = lane; t < cnt; t += 32) {
            unsigned k = __ldg(&cl[t]);
            atomicAdd(&hist[w][min((int)k - (0x8000 + K0RAW + 1), 511)], 1u);
        }
        __syncwarp();
        int hi = 511 - lane * 16;
        unsigned pc = 0;
        #pragma unroll
        for (int t = 0; t < 16; t++) pc += hist[w][hi - t];
        unsigned inc = pc;
        #pragma unroll
        for (int off = 1; off < 32; off <<= 1) {
            unsigned u = __shfl_up_sync(0xffffffffu, inc, off);
            if (lane >= off) inc += u;
        }
        unsigned exc = inc - pc;
        int sel = -1, above = 0;
        if (exc < TOPK && inc >= TOPK) {
            unsigned cum = exc;
            #pragma unroll
            for (int t = 0; t < 16; t++) {
                unsigned c = hist[w][hi - t];
                if (cum + c >= TOPK) { sel = hi - t; above = (int)cum; break; }
                cum += c;
            }
        }
        unsigned fm = __ballot_sync(0xffffffffu, sel >= 0);
        int src = __ffs(fm) - 1;
        sel   = __shfl_sync(0xffffffffu, sel, src);
        above = __shfl_sync(0xffffffffu, above, src);
        if (sel == 511) ok = false;
        else {
            unsigned pref = (unsigned)(0x8000 + K0RAW + 1 + sel);
            int remk = TOPK - above;
            long long isum = 0;
            for (int t = lane; t < cnt; t += 32) {
                unsigned k = __ldg(&cl[t]);
                if (k > pref) isum += ival16(k);
            }
            #pragma unroll
            for (int o = 16; o; o >>= 1) isum += __shfl_xor_sync(0xffffffffu, isum, o);
            if (lane == 0) rowsum = (double)(isum + (long long)remk * ival16(pref)) * (1.0 / 8192.0);
        }
    }

    if (!ok) {
        // ---- rare fallback: recompute row sims, exact 2-pass 8-bit radix ----
        unsigned short keys[256];
        const unsigned* FrW = (const unsigned*)(g_fnb + (size_t)r * DIM);
        for (int t = 0; t < 256; t++) {
            int j = t * 32 + lane;
            const unsigned* FjW = (const unsigned*)(g_fnb + (size_t)j * DIM);
            float s = 0.f;
            for (int d = 0; d < 64; d++) {
                unsigned a = FrW[d], b = __ldg(&FjW[d]);
                s += bflo(a) * bflo(b) + bfhi(a) * bfhi(b);
            }
            unsigned kk = fkey16(pack_bf16x2(s, 0.f) & 0xFFFFu);
            keys[t] = (j == r) ? 0 : (unsigned short)kk;
        }
        unsigned pref2 = 0, pmask2 = 0;
        int rem2 = TOPK;
        for (int shift = 8; shift >= 0; shift -= 8) {
            for (int i = lane; i < 256; i += 32) hist[w][i] = 0;
            __syncwarp();
            for (int t = 0; t < 256; t++) {
                unsigned k = keys[t];
                if ((k & pmask2) == pref2) atomicAdd(&hist[w][(k >> shift) & 255u], 1u);
            }
            __syncwarp();
            int hi = 255 - lane * 8;
            unsigned pc = 0;
            #pragma unroll
            for (int t = 0; t < 8; t++) pc += hist[w][hi - t];
            unsigned inc = pc;
            #pragma unroll
            for (int off = 1; off < 32; off <<= 1) {
                unsigned u = __shfl_up_sync(0xffffffffu, inc, off);
                if (lane >= off) inc += u;
            }
            unsigned exc = inc - pc;
            int sel = -1, above = 0;
            if (exc < (unsigned)rem2 && inc >= (unsigned)rem2) {
                unsigned cum = exc;
                #pragma unroll
                for (int t = 0; t < 8; t++) {
                    unsigned c = hist[w][hi - t];
                    if (cum + c >= (unsigned)rem2) { sel = hi - t; above = (int)cum; break; }
                    cum += c;
                }
            }
            unsigned fm = __ballot_sync(0xffffffffu, sel >= 0);
            int src = __ffs(fm) - 1;
            sel   = __shfl_sync(0xffffffffu, sel, src);
            above = __shfl_sync(0xffffffffu, above, src);
            pref2  |= ((unsigned)sel) << shift;
            pmask2 |= 0xFFu << shift;
            rem2   -= above;
            __syncwarp();
        }
        double ts = 0.0;
        for (int t = 0; t < 256; t++)
            if ((unsigned)keys[t] > pref2) ts += (double)val16(keys[t]);
        #pragma unroll
        for (int o = 16; o; o >>= 1) ts += __shfl_xor_sync(0xffffffffu, ts, o);
        if (lane == 0) rowsum = ts + (double)rem2 * (double)val16(pref2);
    }

    // ---- fused same-label sum via centroid dot ----
    const unsigned* Fr = (const unsigned*)(g_fnb + (size_t)r * DIM);
    unsigned char l = g_lab[r];
    float4 cv = ((const float4*)(g_cent + (size_t)l * DIM))[lane];
    unsigned x0 = Fr[lane * 2], x1 = Fr[lane * 2 + 1];
    float f0 = bflo(x0), f1 = bfhi(x0), f2 = bflo(x1), f3 = bfhi(x1);
    float dot = f0 * cv.x + f1 * cv.y + f2 * cv.z + f3 * cv.w;
    float slf = f0 * f0 + f1 * f1 + f2 * f2 + f3 * f3;
    #pragma unroll
    for (int o = 16; o; o >>= 1) {
        dot += __shfl_xor_sync(0xffffffffu, dot, o);
        slf += __shfl_xor_sync(0xffffffffu, slf, o);
    }
    if (lane == 0) g_partial[r] = (float)(rowsum - (double)(dot - slf));
}

// ============================ final scalar reduce ============================
__global__ void reduce_kernel(float* __restrict__ out) {
    __shared__ double red[256];
    int tid = threadIdx.x;
    double s = 0.0;
    for (int i = tid; i < BN; i += 256) s += (double)g_partial[i];
    red[tid] = s;
    __syncthreads();
    for (int st = 128; st > 0; st >>= 1) {
        if (tid < st) red[tid] += red[tid + st];
        __syncthreads();
    }
    if (tid == 0) out[0] = (float)(red[0] / (double)BN);
}

// ============================ launch ============================
extern "C" void kernel_launch(void* const* d_in, const int* in_sizes, int n_in,
                              void* d_out, int out_size) {
    (void)in_sizes; (void)n_in; (void)out_size;
    const float*    feats = (const float*)d_in[0];
    const unsigned* labw  = (const unsigned*)d_in[1];
    float*          out   = (float*)d_out;

    const int smem = 2 * 128 * ASTR * 2;   // 69632 B
    cudaFuncSetAttribute(gemm_mma_kernel, cudaFuncAttributeMaxDynamicSharedMemorySize, smem);

    prep_kernel<<<1025, 256>>>(feats, labw);
    centroid_kernel<<<256, 256>>>();
    gemm_mma_kernel<<<NTRI, 256, smem>>>();
    select_kernel<<<BN / 16, 512>>>();
    reduce_kernel<<<1, 256>>>(out);
}

// round 17
// speedup vs baseline: 1.3650x; 1.3650x over previous
#include <cuda_runtime.h>
#include <cuda_bf16.h>
#include <cstdint>

#define BN    8192
#define DIM   128
#define TOPK  128
#define CAP   2048
#define ASTR  136
#define NT    64
#define NTRI  (NT * (NT + 1) / 2)   // 2080 triangular tiles
#define K0RAW 0x3E20                // bf16 raw bits of 0.15625
#define KK    ((K0RAW << 16) | K0RAW)

// -------- device scratch --------
__device__ __nv_bfloat16  g_fnb[(size_t)BN * DIM];
__device__ unsigned char  g_lab[BN];
__device__ float          g_cent[256 * DIM];
__device__ int            g_ccnt[BN];
__device__ unsigned short g_cand[(size_t)BN * CAP];   // 32 MB candidate keys
__device__ float          g_partial[BN];

// ============================ helpers ============================
__device__ __forceinline__ uint32_t smem_u32(const void* p) {
    uint32_t a;
    asm("{ .reg .u64 t; cvta.to.shared.u64 t, %1; cvt.u32.u64 %0, t; }" : "=r"(a) : "l"(p));
    return a;
}
__device__ __forceinline__ unsigned pack_bf16x2(float lo, float hi) {
    unsigned r;
    asm("cvt.rn.bf16x2.f32 %0, %1, %2;" : "=r"(r) : "f"(hi), "f"(lo));
    return r;
}
__device__ __forceinline__ void ldmatrix_x4(uint32_t& r0, uint32_t& r1, uint32_t& r2, uint32_t& r3, uint32_t a) {
    asm volatile("ldmatrix.sync.aligned.m8n8.x4.shared.b16 {%0,%1,%2,%3}, [%4];"
                 : "=r"(r0), "=r"(r1), "=r"(r2), "=r"(r3) : "r"(a));
}
__device__ __forceinline__ void ldmatrix_x2(uint32_t& r0, uint32_t& r1, uint32_t a) {
    asm volatile("ldmatrix.sync.aligned.m8n8.x2.shared.b16 {%0,%1}, [%2];"
                 : "=r"(r0), "=r"(r1) : "r"(a));
}
__device__ __forceinline__ void mma_bf16(float* d, const uint32_t* a, const uint32_t* b) {
    asm volatile(
        "mma.sync.aligned.m16n8k16.row.col.f32.bf16.bf16.f32 "
        "{%0,%1,%2,%3}, {%4,%5,%6,%7}, {%8,%9}, {%0,%1,%2,%3};"
        : "+f"(d[0]), "+f"(d[1]), "+f"(d[2]), "+f"(d[3])
        : "r"(a[0]), "r"(a[1]), "r"(a[2]), "r"(a[3]), "r"(b[0]), "r"(b[1]));
}

__device__ __forceinline__ unsigned fkey16(unsigned x) {
    return (x ^ (0x8000u | (0x7FFFu & (0u - (x >> 15))))) & 0xFFFFu;
}
__device__ __forceinline__ float val16(unsigned k) {
    unsigned b = (k & 0x8000u) ? (k ^ 0x8000u) : ((~k) & 0xFFFFu);
    return __uint_as_float(b << 16);
}
// exact fixed-point (val * 2^13) for keys above K0 (exponent >= 124)
__device__ __forceinline__ long long ival16(unsigned k) {
    unsigned raw = k & 0x7FFFu;
    int E = (int)(raw >> 7);
    int M = 128 + (int)(raw & 127u);
    return (long long)M << (E - 121);
}
__device__ __forceinline__ float bflo(unsigned x) { return __uint_as_float(x << 16); }
__device__ __forceinline__ float bfhi(unsigned x) { return __uint_as_float(x & 0xFFFF0000u); }

// ============================ prep: normalize + labels + counter zero ============================
__global__ void prep_kernel(const float* __restrict__ feats, const unsigned* __restrict__ words) {
    if (blockIdx.x == 1024) {
        int tid = threadIdx.x;
        int any = 0;
        for (int i = tid; i < BN / 2; i += blockDim.x) any |= (words[2 * i + 1] != 0u);
        int tot  = __syncthreads_or(any);
        int is64 = (tot == 0);
        for (int i = tid; i < BN; i += blockDim.x)
            g_lab[i] = (unsigned char)(is64 ? words[2 * i] : words[i]);
        for (int i = tid; i < BN; i += blockDim.x) g_ccnt[i] = 0;
        return;
    }
    int w    = (blockIdx.x * blockDim.x + threadIdx.x) >> 5;
    int lane = threadIdx.x & 31;
    float4 v = ((const float4*)(feats + (size_t)w * DIM))[lane];
    float ss = v.x * v.x + v.y * v.y + v.z * v.z + v.w * v.w;
    #pragma unroll
    for (int o = 16; o; o >>= 1) ss += __shfl_xor_sync(0xffffffffu, ss, o);
    float inv = rsqrtf(ss);
    unsigned* dst = (unsigned*)(g_fnb + (size_t)w * DIM);
    dst[lane * 2 + 0] = pack_bf16x2(v.x * inv, v.y * inv);
    dst[lane * 2 + 1] = pack_bf16x2(v.z * inv, v.w * inv);
}

// ============================ class centroids ============================
__global__ void __launch_bounds__(256) centroid_kernel() {
    __shared__ unsigned short idx[BN];
    __shared__ float cpart[2][DIM];
    __shared__ int wcnt8[8];

    int l = blockIdx.x, tid = threadIdx.x, lane = tid & 31, w = tid >> 5;
    unsigned char lc = (unsigned char)l;
    unsigned lw = (unsigned)lc * 0x01010101u;
    const unsigned* LW = (const unsigned*)g_lab;

    int cnt = 0;
    #pragma unroll 4
    for (int k = 0; k < 8; k++) {
        unsigned e = __vcmpeq4(__ldg(&LW[w * 256 + k * 32 + lane]), lw);
        cnt += __popc(e) >> 3;
    }
    #pragma unroll
    for (int o = 16; o; o >>= 1) cnt += __shfl_xor_sync(0xffffffffu, cnt, o);
    if (lane == 0) wcnt8[w] = cnt;
    __syncthreads();

    int base = 0;
    #pragma unroll
    for (int ww = 0; ww < 8; ww++) if (ww < w) base += wcnt8[ww];
    int total = 0;
    #pragma unroll
    for (int ww = 0; ww < 8; ww++) total += wcnt8[ww];

    int pos = base;
    for (int k = 0; k < 32; k++) {
        int j = w * 1024 + k * 32 + lane;
        bool m = (g_lab[j] == lc);
        unsigned bm = __ballot_sync(0xffffffffu, m);
        if (m) idx[pos + __popc(bm & ((1u << lane) - 1u))] = (unsigned short)j;
        pos += __popc(bm);
    }
    __syncthreads();

    int half = tid >> 7;
    int d = tid & 127;
    const unsigned short* F16 = (const unsigned short*)g_fnb;
    float c = 0.f;
    int t = half;
    for (; t + 6 < total; t += 8) {
        float a0 = __uint_as_float(((unsigned)__ldg(&F16[(size_t)idx[t]     * DIM + d])) << 16);
        float a1 = __uint_as_float(((unsigned)__ldg(&F16[(size_t)idx[t + 2] * DIM + d])) << 16);
        float a2 = __uint_as_float(((unsigned)__ldg(&F16[(size_t)idx[t + 4] * DIM + d])) << 16);
        float a3 = __uint_as_float(((unsigned)__ldg(&F16[(size_t)idx[t + 6] * DIM + d])) << 16);
        c += a0; c += a1; c += a2; c += a3;
    }
    for (; t < total; t += 2)
        c += __uint_as_float(((unsigned)__ldg(&F16[(size_t)idx[t] * DIM + d])) << 16);
    cpart[half][d] = c;
    __syncthreads();
    if (tid < DIM) g_cent[l * DIM + tid] = cpart[0][tid] + cpart[1][tid];
}

// ============================ GEMM + atomic-free row-owner candidate filter ============================
__global__ void __launch_bounds__(256, 2) gemm_mma_kernel() {
    int rem = blockIdx.x, tm = 0;
    #pragma unroll 1
    while (rem >= NT - tm) { rem -= NT - tm; tm++; }
    int tn = tm + rem;

    extern __shared__ __align__(16) char sm[];
    __nv_bfloat16* Asm = (__nv_bfloat16*)sm;
    __nv_bfloat16* Bsm = (tm == tn) ? Asm : (__nv_bfloat16*)(sm + 128 * ASTR * 2);

    int tid  = threadIdx.x;
    int wid  = tid >> 5, lane = tid & 31;
    int wm   = wid >> 2, wn = wid & 3;

    const uint4* F = (const uint4*)g_fnb;
    #pragma unroll
    for (int it = 0; it < 8; it++) {
        int i = tid + it * 256;
        int r = i >> 4, g = i & 15;
        *(uint4*)(Asm + r * ASTR + g * 8) = F[(size_t)(tm * 128 + r) * 16 + g];
    }
    if (tm != tn) {
        #pragma unroll
        for (int it = 0; it < 8; it++) {
            int i = tid + it * 256;
            int r = i >> 4, g = i & 15;
            *(uint4*)(Bsm + r * ASTR + g * 8) = F[(size_t)(tn * 128 + r) * 16 + g];
        }
    }
    __syncthreads();

    float acc[4][4][4];
    #pragma unroll
    for (int i = 0; i < 4; i++)
        #pragma unroll
        for (int j = 0; j < 4; j++)
            #pragma unroll
            for (int c = 0; c < 4; c++) acc[i][j][c] = 0.f;

    uint32_t a_base = smem_u32(Asm) + ((wm * 64 + (lane & 15)) * ASTR + (lane >> 4) * 8) * 2;
    uint32_t b_base = smem_u32(Bsm) + ((wn * 32 + (lane & 7)) * ASTR + ((lane >> 3) & 1) * 8) * 2;

    #pragma unroll
    for (int k0 = 0; k0 < DIM; k0 += 16) {
        uint32_t af[4][4], bf[4][2];
        #pragma unroll
        for (int mt = 0; mt < 4; mt++)
            ldmatrix_x4(af[mt][0], af[mt][1], af[mt][2], af[mt][3],
                        a_base + (mt * 16 * ASTR + k0) * 2);
        #pragma unroll
        for (int nt = 0; nt < 4; nt++)
            ldmatrix_x2(bf[nt][0], bf[nt][1],
                        b_base + (nt * 8 * ASTR + k0) * 2);
        #pragma unroll
        for (int mt = 0; mt < 4; mt++)
            #pragma unroll
            for (int nt = 0; nt < 4; nt++)
                mma_bf16(acc[mt][nt], af[mt], bf[nt]);
    }
    __syncthreads();   // A/B smem dead; reuse for staging

    // ---- stage results: bf16 [128][136] + (off-diag) XOR-swizzled transpose ----
    __nv_bfloat16*  stage = (__nv_bfloat16*)sm;                 // 34816 B
    unsigned short* st2   = (unsigned short*)(sm + 34816);      // 32768 B
    bool mir = (tm != tn);

    #pragma unroll
    for (int mt = 0; mt < 4; mt++) {
        int r0 = wm * 64 + mt * 16 + (lane >> 2);
        #pragma unroll
        for (int nt = 0; nt < 4; nt++) {
            int c0 = wn * 32 + nt * 8 + (lane & 3) * 2;
            unsigned p0 = pack_bf16x2(acc[mt][nt][0], acc[mt][nt][1]);
            unsigned p1 = pack_bf16x2(acc[mt][nt][2], acc[mt][nt][3]);
            *(unsigned*)&stage[r0 * ASTR + c0]       = p0;
            *(unsigned*)&stage[(r0 + 8) * ASTR + c0] = p1;
            if (mir) {
                int ra = r0, rb = r0 + 8;
                st2[(c0)     * 128 + (((ra >> 3) ^ (c0 & 15)) * 8)       + (ra & 7)] = (unsigned short)(p0 & 0xFFFF);
                st2[(c0 + 1) * 128 + (((ra >> 3) ^ ((c0 + 1) & 15)) * 8) + (ra & 7)] = (unsigned short)(p0 >> 16);
                st2[(c0)     * 128 + (((rb >> 3) ^ (c0 & 15)) * 8)       + (rb & 7)] = (unsigned short)(p1 & 0xFFFF);
                st2[(c0 + 1) * 128 + (((rb >> 3) ^ ((c0 + 1) & 15)) * 8) + (rb & 7)] = (unsigned short)(p1 >> 16);
            }
        }
    }
    __syncthreads();
    if (!mir && tid < 128) stage[tid * ASTR + tid] = __ushort_as_bfloat16(0);  // diag -> fails filter
    __syncthreads();

    // ---- row-owner scan & publish: 1 global atomic per row per CTA (R15 proven) ----
    if (tid < 128) {
        int t = tid;
        int gm = tm * 128 + t;
        const uint4* row4 = (const uint4*)&stage[t * ASTR];
        int cnt = 0;
        #pragma unroll 4
        for (int i = 0; i < 16; i++) {
            uint4 v = row4[i];
            cnt += __popc(__vcmpgts2(v.x, KK) & 0x80008000u);
            cnt += __popc(__vcmpgts2(v.y, KK) & 0x80008000u);
            cnt += __popc(__vcmpgts2(v.z, KK) & 0x80008000u);
            cnt += __popc(__vcmpgts2(v.w, KK) & 0x80008000u);
        }
        if (cnt > 0) {
            int q = atomicAdd(&g_ccnt[gm], cnt);
            unsigned short* dst = g_cand + (size_t)gm * CAP;
            int w2 = q;
            for (int i = 0; i < 16 && w2 < CAP; i++) {
                uint4 v = row4[i];
                unsigned ps[4] = {v.x, v.y, v.z, v.w};
                #pragma unroll
                for (int k = 0; k < 4; k++) {
                    unsigned p = ps[k];
                    unsigned msk = __vcmpgts2(p, KK);
                    if (msk & 0x8000u)     { if (w2 < CAP) dst[w2] = (unsigned short)(p | 0x8000u); w2++; }
                    if (msk & 0x80000000u) { if (w2 < CAP) dst[w2] = (unsigned short)((p >> 16) | 0x8000u); w2++; }
                }
            }
        }
    } else if (mir) {
        int t = tid - 128;
        int gn = tn * 128 + t;
        int cnt = 0;
        #pragma unroll 4
        for (int g = 0; g < 16; g++) {
            int pg = g ^ (t & 15);
            uint4 v = *(const uint4*)&st2[t * 128 + pg * 8];
            cnt += __popc(__vcmpgts2(v.x, KK) & 0x80008000u);
            cnt += __popc(__vcmpgts2(v.y, KK) & 0x80008000u);
            cnt += __popc(__vcmpgts2(v.z, KK) & 0x80008000u);
            cnt += __popc(__vcmpgts2(v.w, KK) & 0x80008000u);
        }
        if (cnt > 0) {
            int q = atomicAdd(&g_ccnt[gn], cnt);
            unsigned short* dst = g_cand + (size_t)gn * CAP;
            int w2 = q;
            for (int g = 0; g < 16 && w2 < CAP; g++) {
                int pg = g ^ (t & 15);
                uint4 v = *(const uint4*)&st2[t * 128 + pg * 8];
                unsigned ps[4] = {v.x, v.y, v.z, v.w};
                #pragma unroll
                for (int k = 0; k < 4; k++) {
                    unsigned p = ps[k];
                    unsigned msk = __vcmpgts2(p, KK);
                    if (msk & 0x8000u)     { if (w2 < CAP) dst[w2] = (unsigned short)(p | 0x8000u); w2++; }
                    if (msk & 0x80000000u) { if (w2 < CAP) dst[w2] = (unsigned short)((p >> 16) | 0x8000u); w2++; }
                }
            }
        }
    }
}

// ============================ select: warp per row over candidate lists ============================
__global__ void __launch_bounds__(512) select_kernel() {
    __shared__ unsigned hist[16][512];   // 32 KB

    int tid = threadIdx.x, lane = tid & 31, w = tid >> 5;
    int r = blockIdx.x * 16 + w;

    int cnt = g_ccnt[r];
    const unsigned short* cl = g_cand + (size_t)r * CAP;
    bool ok = (cnt >= TOPK && cnt <= CAP);
    double rowsum = 0.0;                  // valid on lane 0

    if (ok) {
        #pragma unroll
        for (int i = lane; i < 512; i += 32) hist[w][i] = 0;
        __syncwarp();
        for (int t = lane; t < cnt; t += 32) {
            unsigned k = __ldg(&cl[t]);
            atomicAdd(&hist[w][min((int)k - (0x8000 + K0RAW + 1), 511)], 1u);
        }
        __syncwarp();
        int hi = 511 - lane * 16;
        unsigned pc = 0;
        #pragma unroll
        for (int t = 0; t < 16; t++) pc += hist[w][hi - t];
        unsigned inc = pc;
        #pragma unroll
        for (int off = 1; off < 32; off <<= 1) {
            unsigned u = __shfl_up_sync(0xffffffffu, inc, off);
            if (lane >= off) inc += u;
        }
        unsigned exc = inc - pc;
        int sel = -1, above = 0;
        if (exc < TOPK && inc >= TOPK) {
            unsigned cum = exc;
            #pragma unroll
            for (int t = 0; t < 16; t++) {
                unsigned c = hist[w][hi - t];
                if (cum + c >= TOPK) { sel = hi - t; above = (int)cum; break; }
                cum += c;
            }
        }
        unsigned fm = __ballot_sync(0xffffffffu, sel >= 0);
        int src = __ffs(fm) - 1;
        sel   = __shfl_sync(0xffffffffu, sel, src);
        above = __shfl_sync(0xffffffffu, above, src);
        if (sel == 511) ok = false;
        else {
            unsigned pref = (unsigned)(0x8000 + K0RAW + 1 + sel);
            int remk = TOPK - above;
            long long isum = 0;
            for (int t = lane; t < cnt; t += 32) {
                unsigned k = __ldg(&cl[t]);
                if (k > pref) isum += ival16(k);
            }
            #pragma unroll
            for (int o = 16; o; o >>= 1) isum += __shfl_xor_sync(0xffffffffu, isum, o);
            if (lane == 0) rowsum = (double)(isum + (long long)remk * ival16(pref)) * (1.0 / 8192.0);
        }
    }

    if (!ok) {
        // ---- rare fallback: recompute row sims, exact 2-pass 8-bit radix ----
        unsigned short keys[256];
        const unsigned* FrW = (const unsigned*)(g_fnb + (size_t)r * DIM);
        for (int t = 0; t < 256; t++) {
            int j = t * 32 + lane;
            const unsigned* FjW = (const unsigned*)(g_fnb + (size_t)j * DIM);
            float s = 0.f;
            for (int d = 0; d < 64; d++) {
                unsigned a = FrW[d], b = __ldg(&FjW[d]);
                s += bflo(a) * bflo(b) + bfhi(a) * bfhi(b);
            }
            unsigned kk = fkey16(pack_bf16x2(s, 0.f) & 0xFFFFu);
            keys[t] = (j == r) ? 0 : (unsigned short)kk;
        }
        unsigned pref2 = 0, pmask2 = 0;
        int rem2 = TOPK;
        for (int shift = 8; shift >= 0; shift -= 8) {
            for (int i = lane; i < 256; i += 32) hist[w][i] = 0;
            __syncwarp();
            for (int t = 0; t < 256; t++) {
                unsigned k = keys[t];
                if ((k & pmask2) == pref2) atomicAdd(&hist[w][(k >> shift) & 255u], 1u);
            }
            __syncwarp();
            int hi = 255 - lane * 8;
            unsigned pc = 0;
            #pragma unroll
            for (int t = 0; t < 8; t++) pc += hist[w][hi - t];
            unsigned inc = pc;
            #pragma unroll
            for (int off = 1; off < 32; off <<= 1) {
                unsigned u = __shfl_up_sync(0xffffffffu, inc, off);
                if (lane >= off) inc += u;
            }
            unsigned exc = inc - pc;
            int sel = -1, above = 0;
            if (exc < (unsigned)rem2 && inc >= (unsigned)rem2) {
                unsigned cum = exc;
                #pragma unroll
                for (int t = 0; t < 8; t++) {
                    unsigned c = hist[w][hi - t];
                    if (cum + c >= (unsigned)rem2) { sel = hi - t; above = (int)cum; break; }
                    cum += c;
                }
            }
            unsigned fm = __ballot_sync(0xffffffffu, sel >= 0);
            int src = __ffs(fm) - 1;
            sel   = __shfl_sync(0xffffffffu, sel, src);
            above = __shfl_sync(0xffffffffu, above, src);
            pref2  |= ((unsigned)sel) << shift;
            pmask2 |= 0xFFu << shift;
            rem2   -= above;
            __syncwarp();
        }
        double ts = 0.0;
        for (int t = 0; t < 256; t++)
            if ((unsigned)keys[t] > pref2) ts += (double)val16(keys[t]);
        #pragma unroll
        for (int o = 16; o; o >>= 1) ts += __shfl_xor_sync(0xffffffffu, ts, o);
        if (lane == 0) rowsum = ts + (double)rem2 * (double)val16(pref2);
    }

    // ---- fused same-label sum via centroid dot ----
    const unsigned* Fr = (const unsigned*)(g_fnb + (size_t)r * DIM);
    unsigned char l = g_lab[r];
    float4 cv = ((const float4*)(g_cent + (size_t)l * DIM))[lane];
    unsigned x0 = Fr[lane * 2], x1 = Fr[lane * 2 + 1];
    float f0 = bflo(x0), f1 = bfhi(x0), f2 = bflo(x1), f3 = bfhi(x1);
    float dot = f0 * cv.x + f1 * cv.y + f2 * cv.z + f3 * cv.w;
    float slf = f0 * f0 + f1 * f1 + f2 * f2 + f3 * f3;
    #pragma unroll
    for (int o = 16; o; o >>= 1) {
        dot += __shfl_xor_sync(0xffffffffu, dot, o);
        slf += __shfl_xor_sync(0xffffffffu, slf, o);
    }
    if (lane == 0) g_partial[r] = (float)(rowsum - (double)(dot - slf));
}

// ============================ final scalar reduce ============================
__global__ void reduce_kernel(float* __restrict__ out) {
    __shared__ double red[256];
    int tid = threadIdx.x;
    double s = 0.0;
    for (int i = tid; i < BN; i += 256) s += (double)g_partial[i];
    red[tid] = s;
    __syncthreads();
    for (int st = 128; st > 0; st >>= 1) {
        if (tid < st) red[tid] += red[tid + st];
        __syncthreads();
    }
    if (tid == 0) out[0] = (float)(red[0] / (double)BN);
}

// ============================ launch ============================
extern "C" void kernel_launch(void* const* d_in, const int* in_sizes, int n_in,
                              void* d_out, int out_size) {
    (void)in_sizes; (void)n_in; (void)out_size;
    const float*    feats = (const float*)d_in[0];
    const unsigned* labw  = (const unsigned*)d_in[1];
    float*          out   = (float*)d_out;

    const int smem = 2 * 128 * ASTR * 2;   // 69632 B
    cudaFuncSetAttribute(gemm_mma_kernel, cudaFuncAttributeMaxDynamicSharedMemorySize, smem);

    prep_kernel<<<1025, 256>>>(feats, labw);
    centroid_kernel<<<256, 256>>>();
    gemm_mma_kernel<<<NTRI, 256, smem>>>();
    select_kernel<<<BN / 16, 512>>>();
    reduce_kernel<<<1, 256>>>(out);
}